// round 2
// baseline (speedup 1.0000x reference)
#include <cuda_runtime.h>

#define BB 8
#define NN 262144
#define PRE 6000
#define PROP 1000
#define NBUCK 65536
#define CAND_CAP 8192
#define ROWCAP 256
#define MASKW 188   // ceil(6000/32)

// ---------------- scratch (device globals; no allocation allowed) ----------------
__device__ unsigned int        g_hist[BB * NBUCK];          // 2 MB
__device__ int                 g_cand_cnt[BB];
__device__ int                 g_thresh[BB];
__device__ unsigned long long  g_cand[BB * CAND_CAP];       // 512 KB
__device__ float4              g_boxes[BB * PRE];           // 768 KB
__device__ float               g_area[BB * PRE];
__device__ int                 g_rowcnt[BB * PRE];
__device__ int                 g_rowlist[(size_t)BB * PRE * ROWCAP];  // ~49 MB

// ---------------- K0: zero scratch counters ----------------
__global__ void zero_kernel() {
    int i = blockIdx.x * blockDim.x + threadIdx.x;
    if (i < BB * NBUCK) {
        g_hist[i] = 0u;
    } else {
        int j = i - BB * NBUCK;
        if (j < BB * PRE) {
            g_rowcnt[j] = 0;
        } else {
            int k = j - BB * PRE;
            if (k < BB) g_cand_cnt[k] = 0;
        }
    }
}

// ---------------- K1: histogram of scores (65536 buckets / batch) ----------------
__global__ void hist_kernel(const float* __restrict__ probs) {
    int g = blockIdx.x * 256 + threadIdx.x;          // exactly BB*NN threads
    float s = probs[(size_t)g * 2 + 1];
    int bk = (int)(s * 65536.0f);
    bk = max(0, min(bk, NBUCK - 1));
    int b = g >> 18;                                  // NN = 2^18
    atomicAdd(&g_hist[b * NBUCK + bk], 1u);
}

// ---------------- K2: find threshold bucket (suffix count >= PRE) ----------------
__global__ void thresh_kernel() {
    __shared__ int part[1024];
    int b = blockIdx.x, t = threadIdx.x;
    const unsigned int* h = &g_hist[b * NBUCK];
    int hi = NBUCK - t * 64 - 1;                      // top bucket of this thread's chunk
    int s = 0;
    #pragma unroll 8
    for (int k = 0; k < 64; ++k) s += (int)h[hi - k];
    part[t] = s;
    __syncthreads();
    int mysum = s;
    for (int off = 1; off < 1024; off <<= 1) {
        int v = (t >= off) ? part[t - off] : 0;
        __syncthreads();
        part[t] += v;
        __syncthreads();
    }
    int incl = part[t], excl = incl - mysum;
    if (excl < PRE && incl >= PRE) {
        int running = excl;
        for (int bk = hi; bk > hi - 64; --bk) {
            running += (int)h[bk];
            if (running >= PRE) { g_thresh[b] = bk; break; }
        }
    }
}

// ---------------- K3: compact candidates above threshold ----------------
__global__ void compact_kernel(const float* __restrict__ probs) {
    int g = blockIdx.x * 256 + threadIdx.x;
    float s = probs[(size_t)g * 2 + 1];
    int bk = (int)(s * 65536.0f);
    bk = max(0, min(bk, NBUCK - 1));
    int b = g >> 18;
    if (bk >= g_thresh[b]) {
        int pos = atomicAdd(&g_cand_cnt[b], 1);
        if (pos < CAND_CAP) {
            unsigned int n = (unsigned int)(g & (NN - 1));
            g_cand[b * CAND_CAP + pos] =
                ((unsigned long long)__float_as_uint(s) << 32) | (unsigned int)(~n);
        }
    }
}

// ---------------- K4: bitonic sort (desc) + box decode/clip ----------------
__global__ void sort_decode_kernel(const float* __restrict__ bbox,
                                   const float* __restrict__ anchors) {
    extern __shared__ unsigned long long sk[];
    int b = blockIdx.x, t = threadIdx.x;
    int M = g_cand_cnt[b];
    if (M > CAND_CAP) M = CAND_CAP;
    for (int i = t; i < CAND_CAP; i += blockDim.x)
        sk[i] = (i < M) ? g_cand[b * CAND_CAP + i] : 0ULL;
    __syncthreads();
    for (int k = 2; k <= CAND_CAP; k <<= 1) {
        for (int j = k >> 1; j > 0; j >>= 1) {
            for (int i = t; i < CAND_CAP; i += blockDim.x) {
                int ixj = i ^ j;
                if (ixj > i) {
                    unsigned long long a = sk[i], c = sk[ixj];
                    bool sw = ((i & k) == 0) ? (a < c) : (a > c);   // descending overall
                    if (sw) { sk[i] = c; sk[ixj] = a; }
                }
            }
            __syncthreads();
        }
    }
    // decode top PRE: mirror reference op order exactly (no FMA contraction)
    for (int jj = t; jj < PRE; jj += blockDim.x) {
        unsigned long long key = sk[jj];
        unsigned int n = ~(unsigned int)(key & 0xFFFFFFFFull);
        size_t base = (size_t)b * NN + n;
        float4 a = ((const float4*)anchors)[base];   // (y1,x1,y2,x2)
        float4 r = ((const float4*)bbox)[base];
        float d0 = __fmul_rn(r.x, 0.1f), d1 = __fmul_rn(r.y, 0.1f);
        float d2 = __fmul_rn(r.z, 0.2f), d3 = __fmul_rn(r.w, 0.2f);
        float hh = __fsub_rn(a.z, a.x), ww = __fsub_rn(a.w, a.y);
        float cy = __fadd_rn(a.x, __fmul_rn(0.5f, hh));
        float cx = __fadd_rn(a.y, __fmul_rn(0.5f, ww));
        cy = __fadd_rn(cy, __fmul_rn(d0, hh));
        cx = __fadd_rn(cx, __fmul_rn(d1, ww));
        hh = __fmul_rn(hh, expf(d2));
        ww = __fmul_rn(ww, expf(d3));
        float y1 = __fsub_rn(cy, __fmul_rn(0.5f, hh));
        float x1 = __fsub_rn(cx, __fmul_rn(0.5f, ww));
        float y2 = __fadd_rn(cy, __fmul_rn(0.5f, hh));
        float x2 = __fadd_rn(cx, __fmul_rn(0.5f, ww));
        y1 = fminf(fmaxf(y1, 0.f), 1.f);
        x1 = fminf(fmaxf(x1, 0.f), 1.f);
        y2 = fminf(fmaxf(y2, 0.f), 1.f);
        x2 = fminf(fmaxf(x2, 0.f), 1.f);
        g_boxes[b * PRE + jj] = make_float4(y1, x1, y2, x2);
        g_area[b * PRE + jj] = __fmul_rn(__fsub_rn(y2, y1), __fsub_rn(x2, x1));
    }
}

// ---------------- K5: sparse suppression pairs (i<j, IoU>0.7) ----------------
__global__ void pairs_kernel() {
    int ti = blockIdx.x, tj = blockIdx.y, b = blockIdx.z;
    if (tj < ti) return;                  // upper triangular tiles only
    __shared__ float4 sbi[128], sbj[128];
    __shared__ float  sai[128], saj[128];
    int t = threadIdx.x;
    int i0 = ti * 128, j0 = tj * 128;
    if (t < 128) {
        int gi = i0 + t;
        if (gi < PRE) { sbi[t] = g_boxes[b * PRE + gi]; sai[t] = g_area[b * PRE + gi]; }
        else          { sbi[t] = make_float4(0, 0, 0, 0); sai[t] = 0.f; }
    } else {
        int tt = t - 128, gj = j0 + tt;
        if (gj < PRE) { sbj[tt] = g_boxes[b * PRE + gj]; saj[tt] = g_area[b * PRE + gj]; }
        else          { sbj[tt] = make_float4(0, 0, 0, 0); saj[tt] = 0.f; }
    }
    __syncthreads();
    int ii = t & 127;
    int gi = i0 + ii;
    if (gi >= PRE) return;
    float4 bi = sbi[ii];
    float  ai = sai[ii];
    for (int jj = (t >> 7); jj < 128; jj += 2) {
        int gj = j0 + jj;
        if (gj <= gi || gj >= PRE) continue;
        float4 bj = sbj[jj];
        float yy1 = fmaxf(bi.x, bj.x), xx1 = fmaxf(bi.y, bj.y);
        float yy2 = fminf(bi.z, bj.z), xx2 = fminf(bi.w, bj.w);
        float ihh = __fsub_rn(yy2, yy1), iww = __fsub_rn(xx2, xx1);
        if (ihh <= 0.f || iww <= 0.f) continue;       // inter == 0 -> iou 0
        float inter = __fmul_rn(ihh, iww);
        float den = __fadd_rn(__fsub_rn(__fadd_rn(ai, saj[jj]), inter), 1e-8f);
        if (__fdiv_rn(inter, den) > 0.7f) {
            int pos = atomicAdd(&g_rowcnt[b * PRE + gi], 1);
            if (pos < ROWCAP)
                g_rowlist[((size_t)(b * PRE + gi)) * ROWCAP + pos] = gj;
        }
    }
}

// ---------------- K6: serial greedy over sparse lists + output ----------------
__global__ void greedy_kernel(float4* __restrict__ out) {
    __shared__ unsigned int mask[MASKW];
    __shared__ int scnt[PRE];
    __shared__ int sel[PROP];
    __shared__ int s_nsel;
    int b = blockIdx.x, t = threadIdx.x;
    for (int i = t; i < MASKW; i += blockDim.x)
        mask[i] = (i < 187) ? 0xFFFFFFFFu : 0x0000FFFFu;   // 187*32+16 = 6000 bits
    for (int i = t; i < PRE; i += blockDim.x)
        scnt[i] = g_rowcnt[b * PRE + i];
    __syncthreads();
    if (t == 0) {
        int nsel = 0;
        for (int wd = 0; wd < MASKW && nsel < PROP; ++wd) {
            unsigned int word = mask[wd];
            while (word) {
                int bit = __ffs(word) - 1;
                word &= word - 1;
                int i = wd * 32 + bit;
                sel[nsel++] = i;
                if (nsel == PROP) break;
                int c = scnt[i];
                if (c > ROWCAP) c = ROWCAP;
                if (c > 0) {
                    const int* lst = &g_rowlist[((size_t)(b * PRE + i)) * ROWCAP];
                    for (int e = 0; e < c; ++e) {
                        int j = lst[e];                 // j > i always
                        int jw = j >> 5;
                        unsigned int bm = ~(1u << (j & 31));
                        if (jw == wd) word &= bm;
                        else mask[jw] &= bm;
                    }
                }
            }
        }
        s_nsel = nsel;
    }
    __syncthreads();
    int nsel = s_nsel;
    for (int k = t; k < PROP; k += blockDim.x)
        out[b * PROP + k] = (k < nsel) ? g_boxes[b * PRE + sel[k]]
                                       : make_float4(0.f, 0.f, 0.f, 0.f);
}

// ---------------- launch ----------------
extern "C" void kernel_launch(void* const* d_in, const int* in_sizes, int n_in,
                              void* d_out, int out_size) {
    const float* probs   = (const float*)d_in[0];
    const float* bbox    = (const float*)d_in[1];
    const float* anchors = (const float*)d_in[2];

    cudaFuncSetAttribute(sort_decode_kernel,
                         cudaFuncAttributeMaxDynamicSharedMemorySize, CAND_CAP * 8);

    int zeroTot = BB * NBUCK + BB * PRE + BB;
    zero_kernel<<<(zeroTot + 255) / 256, 256>>>();
    hist_kernel<<<(BB * NN) / 256, 256>>>(probs);
    thresh_kernel<<<BB, 1024>>>();
    compact_kernel<<<(BB * NN) / 256, 256>>>(probs);
    sort_decode_kernel<<<BB, 1024, CAND_CAP * 8>>>(bbox, anchors);
    pairs_kernel<<<dim3(47, 47, BB), 256>>>();
    greedy_kernel<<<BB, 256>>>((float4*)d_out);
}

// round 3
// speedup vs baseline: 1.7204x; 1.7204x over previous
#include <cuda_runtime.h>

#define BB 8
#define NN 262144
#define PRE 6000
#define PROP 1000
#define NBUCK 65536
#define CAP 16384
#define IMAX 2048
#define ROWCAP 64
#define MW1 (IMAX / 32)   // 64
#define MWF 188           // ceil(6000/32)

// ---------------- scratch ----------------
__device__ unsigned int       g_hist[BB * NBUCK];    // bucket counts (also scatter base)
__device__ unsigned int       g_scat[BB * NBUCK];    // scatter counters
__device__ unsigned int       g_off[BB * NBUCK];     // exclusive suffix offsets
__device__ int                g_thresh[BB];
__device__ int                g_need_full[BB];
__device__ unsigned long long g_sorted[BB * CAP];    // descending keys
__device__ float4             g_boxes[BB * PRE];
__device__ float              g_area[BB * PRE];
__device__ int                g_rowcnt[BB * IMAX];
__device__ int                g_rowlist[BB * IMAX * ROWCAP];

// ---------------- K0: zero counters ----------------
__global__ void zero_kernel() {
    int i = blockIdx.x * blockDim.x + threadIdx.x;
    int H = BB * NBUCK;
    if (i < H) { g_hist[i] = 0u; return; }
    i -= H;
    if (i < H) { g_scat[i] = 0u; return; }
    i -= H;
    if (i < BB * IMAX) { g_rowcnt[i] = 0; return; }
    i -= BB * IMAX;
    if (i < BB) g_need_full[i] = 0;
}

__device__ __forceinline__ int bucket_of(float s) {
    int bk = (int)(s * 65536.0f);
    return max(0, min(bk, NBUCK - 1));
}

// ---------------- K1: histogram (float4: 2 scores per load) ----------------
__global__ void hist_kernel(const float* __restrict__ probs) {
    int g = blockIdx.x * 256 + threadIdx.x;            // BB*NN/2 threads
    float4 v = ((const float4*)probs)[g];              // (p0,s0,p1,s1)
    int b = g >> 17;                                   // NN/2 = 2^17 float4 per batch
    atomicAdd(&g_hist[b * NBUCK + bucket_of(v.y)], 1u);
    atomicAdd(&g_hist[b * NBUCK + bucket_of(v.w)], 1u);
}

// ---------------- K2: suffix-scan -> offsets + threshold ----------------
__global__ void scan_kernel() {
    __shared__ int part[1024];
    int b = blockIdx.x, t = threadIdx.x;
    const unsigned int* h = &g_hist[b * NBUCK];
    unsigned int* off = &g_off[b * NBUCK];
    // chunk t covers the t-th 64-bucket chunk from the TOP (descending)
    int top = NBUCK - t * 64 - 1;
    int s = 0;
    #pragma unroll 8
    for (int k = 0; k < 64; ++k) s += (int)h[top - k];
    part[t] = s;
    __syncthreads();
    int mysum = s;
    for (int o = 1; o < 1024; o <<= 1) {
        int v = (t >= o) ? part[t - o] : 0;
        __syncthreads();
        part[t] += v;
        __syncthreads();
    }
    int running = part[t] - mysum;                     // count strictly above chunk
    for (int bk = top; bk > top - 64; --bk) {
        unsigned int c = h[bk];
        off[bk] = (unsigned int)running;
        if (running < PRE && running + (int)c >= PRE) g_thresh[b] = bk;
        running += (int)c;
    }
}

// ---------------- K3: scatter candidates into bucket segments ----------------
__global__ void scatter_kernel(const float* __restrict__ probs) {
    int g = blockIdx.x * 256 + threadIdx.x;
    float4 v = ((const float4*)probs)[g];
    int b = g >> 17;
    int th = g_thresh[b];
    unsigned int n0 = (unsigned int)((g & 131071) * 2);
    #pragma unroll
    for (int e = 0; e < 2; ++e) {
        float s = e ? v.w : v.y;
        unsigned int n = n0 + e;
        int bk = bucket_of(s);
        if (bk >= th) {
            unsigned int pos = g_off[b * NBUCK + bk] +
                               atomicAdd(&g_scat[b * NBUCK + bk], 1u);
            if (pos < CAP)
                g_sorted[b * CAP + pos] =
                    ((unsigned long long)__float_as_uint(s) << 32) | (~n);
        }
    }
}

// ---------------- K4: per-bucket insertion sort (descending) ----------------
__global__ void bsort_kernel() {
    int g = blockIdx.x * 256 + threadIdx.x;            // BB*NBUCK threads
    int b = g >> 16, bk = g & (NBUCK - 1);
    if (bk < g_thresh[b]) return;
    int cnt = (int)g_hist[b * NBUCK + bk];
    if (cnt <= 1) return;
    int s0 = (int)g_off[b * NBUCK + bk];
    if (s0 >= CAP) return;
    int e0 = min(s0 + cnt, CAP);
    unsigned long long* a = &g_sorted[b * CAP];
    for (int i = s0 + 1; i < e0; ++i) {
        unsigned long long key = a[i];
        int j = i - 1;
        while (j >= s0 && a[j] < key) { a[j + 1] = a[j]; --j; }
        a[j + 1] = key;
    }
}

// ---------------- K5: decode top-PRE boxes (exact reference arithmetic) ----------------
__global__ void decode_kernel(const float* __restrict__ bbox,
                              const float* __restrict__ anchors) {
    int j = blockIdx.x * 256 + threadIdx.x;
    int b = blockIdx.y;
    if (j >= PRE) return;
    unsigned long long key = g_sorted[b * CAP + j];
    unsigned int n = ~(unsigned int)(key & 0xFFFFFFFFull);
    size_t base = (size_t)b * NN + n;
    float4 a = ((const float4*)anchors)[base];
    float4 r = ((const float4*)bbox)[base];
    float d0 = __fmul_rn(r.x, 0.1f), d1 = __fmul_rn(r.y, 0.1f);
    float d2 = __fmul_rn(r.z, 0.2f), d3 = __fmul_rn(r.w, 0.2f);
    float hh = __fsub_rn(a.z, a.x), ww = __fsub_rn(a.w, a.y);
    float cy = __fadd_rn(a.x, __fmul_rn(0.5f, hh));
    float cx = __fadd_rn(a.y, __fmul_rn(0.5f, ww));
    cy = __fadd_rn(cy, __fmul_rn(d0, hh));
    cx = __fadd_rn(cx, __fmul_rn(d1, ww));
    hh = __fmul_rn(hh, expf(d2));
    ww = __fmul_rn(ww, expf(d3));
    float y1 = __fsub_rn(cy, __fmul_rn(0.5f, hh));
    float x1 = __fsub_rn(cx, __fmul_rn(0.5f, ww));
    float y2 = __fadd_rn(cy, __fmul_rn(0.5f, hh));
    float x2 = __fadd_rn(cx, __fmul_rn(0.5f, ww));
    y1 = fminf(fmaxf(y1, 0.f), 1.f);
    x1 = fminf(fmaxf(x1, 0.f), 1.f);
    y2 = fminf(fmaxf(y2, 0.f), 1.f);
    x2 = fminf(fmaxf(x2, 0.f), 1.f);
    g_boxes[b * PRE + j] = make_float4(y1, x1, y2, x2);
    g_area[b * PRE + j] = __fmul_rn(__fsub_rn(y2, y1), __fsub_rn(x2, x1));
}

// ---------------- K6: suppression pairs, i<j < IMAX only ----------------
__global__ void pairs_kernel() {
    int ti = blockIdx.x, tj = blockIdx.y, b = blockIdx.z;
    if (tj < ti) return;
    __shared__ float4 sbi[128], sbj[128];
    __shared__ float  sai[128], saj[128];
    int t = threadIdx.x;
    int i0 = ti * 128, j0 = tj * 128;
    if (t < 128) {
        sbi[t] = g_boxes[b * PRE + i0 + t];
        sai[t] = g_area[b * PRE + i0 + t];
    } else {
        int tt = t - 128;
        sbj[tt] = g_boxes[b * PRE + j0 + tt];
        saj[tt] = g_area[b * PRE + j0 + tt];
    }
    __syncthreads();
    int ii = t & 127;
    int gi = i0 + ii;
    float4 bi = sbi[ii];
    float  ai = sai[ii];
    for (int jj = (t >> 7); jj < 128; jj += 2) {
        int gj = j0 + jj;
        if (gj <= gi) continue;
        float4 bj = sbj[jj];
        float yy1 = fmaxf(bi.x, bj.x), xx1 = fmaxf(bi.y, bj.y);
        float yy2 = fminf(bi.z, bj.z), xx2 = fminf(bi.w, bj.w);
        float ihh = __fsub_rn(yy2, yy1), iww = __fsub_rn(xx2, xx1);
        if (ihh <= 0.f || iww <= 0.f) continue;
        float inter = __fmul_rn(ihh, iww);
        float den = __fadd_rn(__fsub_rn(__fadd_rn(ai, saj[jj]), inter), 1e-8f);
        if (__fdiv_rn(inter, den) > 0.7f) {
            int pos = atomicAdd(&g_rowcnt[b * IMAX + gi], 1);
            if (pos < ROWCAP)
                g_rowlist[(b * IMAX + gi) * ROWCAP + pos] = gj;
        }
    }
}

// ---------------- K7: fast greedy over [0, IMAX); flags fallback if insufficient ----------------
__global__ void greedy_kernel(float4* __restrict__ out) {
    __shared__ unsigned int mask[MW1];
    __shared__ int scnt[IMAX];
    __shared__ int sel[PROP];
    __shared__ int s_nsel, s_flag;
    int b = blockIdx.x, t = threadIdx.x;
    for (int i = t; i < MW1; i += blockDim.x) mask[i] = 0xFFFFFFFFu;
    for (int i = t; i < IMAX; i += blockDim.x) scnt[i] = g_rowcnt[b * IMAX + i];
    __syncthreads();
    if (t == 0) {
        int nsel = 0, bad = 0;
        for (int wd = 0; wd < MW1 && nsel < PROP && !bad; ++wd) {
            unsigned int word = mask[wd];
            while (word) {
                int bit = __ffs(word) - 1;
                word &= word - 1;
                int i = wd * 32 + bit;
                int c = scnt[i];
                if (c > ROWCAP) { bad = 1; break; }
                sel[nsel++] = i;
                if (nsel == PROP) break;
                const int* lst = &g_rowlist[(b * IMAX + i) * ROWCAP];
                for (int e = 0; e < c; ++e) {
                    int j = lst[e];                    // j > i always
                    int jw = j >> 5;
                    unsigned int bm = ~(1u << (j & 31));
                    if (jw == wd) word &= bm;
                    else mask[jw] &= bm;
                }
            }
        }
        if (nsel < PROP) bad = 1;                      // conservatively need full NMS
        s_flag = bad;
        s_nsel = nsel;
        if (bad) g_need_full[b] = 1;
    }
    __syncthreads();
    if (s_flag) return;                                // fallback kernel will write
    int nsel = s_nsel;
    for (int k = t; k < PROP; k += blockDim.x)
        out[b * PROP + k] = (k < nsel) ? g_boxes[b * PRE + sel[k]]
                                       : make_float4(0.f, 0.f, 0.f, 0.f);
}

// ---------------- K8: exact full greedy fallback (normally a no-op) ----------------
__global__ void greedy_full_kernel(float4* __restrict__ out) {
    int b = blockIdx.x, t = threadIdx.x;
    if (!g_need_full[b]) return;
    __shared__ unsigned int mask[MWF];
    __shared__ int sel[PROP];
    __shared__ int s_pivot, s_nsel;
    for (int i = t; i < MWF; i += blockDim.x)
        mask[i] = (i < 187) ? 0xFFFFFFFFu : 0x0000FFFFu;  // 6000 bits
    if (t == 0) s_nsel = 0;
    __syncthreads();
    while (true) {
        if (t == 0) {
            int p = -1;
            if (s_nsel < PROP) {
                for (int wd = 0; wd < MWF; ++wd) {
                    unsigned int w = mask[wd];
                    if (w) { p = wd * 32 + __ffs(w) - 1; break; }
                }
            }
            s_pivot = p;
            if (p >= 0) { sel[s_nsel] = p; s_nsel++; }
        }
        __syncthreads();
        int p = s_pivot;
        if (p < 0) break;
        float4 bp = g_boxes[b * PRE + p];
        float  ap = g_area[b * PRE + p];
        if (t == 0) atomicAnd(&mask[p >> 5], ~(1u << (p & 31)));  // self-suppress
        for (int j = p + 1 + t; j < PRE; j += blockDim.x) {
            if (!((mask[j >> 5] >> (j & 31)) & 1u)) continue;
            float4 bj = g_boxes[b * PRE + j];
            float yy1 = fmaxf(bp.x, bj.x), xx1 = fmaxf(bp.y, bj.y);
            float yy2 = fminf(bp.z, bj.z), xx2 = fminf(bp.w, bj.w);
            float ihh = __fsub_rn(yy2, yy1), iww = __fsub_rn(xx2, xx1);
            if (ihh <= 0.f || iww <= 0.f) continue;
            float inter = __fmul_rn(ihh, iww);
            float den = __fadd_rn(__fsub_rn(__fadd_rn(ap, g_area[b * PRE + j]), inter), 1e-8f);
            if (__fdiv_rn(inter, den) > 0.7f)
                atomicAnd(&mask[j >> 5], ~(1u << (j & 31)));
        }
        __syncthreads();
    }
    int nsel = s_nsel;
    for (int k = t; k < PROP; k += blockDim.x)
        out[b * PROP + k] = (k < nsel) ? g_boxes[b * PRE + sel[k]]
                                       : make_float4(0.f, 0.f, 0.f, 0.f);
}

// ---------------- launch ----------------
extern "C" void kernel_launch(void* const* d_in, const int* in_sizes, int n_in,
                              void* d_out, int out_size) {
    const float* probs   = (const float*)d_in[0];
    const float* bbox    = (const float*)d_in[1];
    const float* anchors = (const float*)d_in[2];

    int zeroTot = 2 * BB * NBUCK + BB * IMAX + BB;
    zero_kernel<<<(zeroTot + 255) / 256, 256>>>();
    hist_kernel<<<(BB * NN / 2) / 256, 256>>>(probs);
    scan_kernel<<<BB, 1024>>>();
    scatter_kernel<<<(BB * NN / 2) / 256, 256>>>(probs);
    bsort_kernel<<<(BB * NBUCK) / 256, 256>>>();
    decode_kernel<<<dim3((PRE + 255) / 256, BB), 256>>>(bbox, anchors);
    pairs_kernel<<<dim3(IMAX / 128, IMAX / 128, BB), 256>>>();
    greedy_kernel<<<BB, 256>>>((float4*)d_out);
    greedy_full_kernel<<<BB, 256>>>((float4*)d_out);
}

// round 5
// speedup vs baseline: 1.9782x; 1.1499x over previous
#include <cuda_runtime.h>

#define BB 8
#define NN 262144
#define PRE 6000
#define PROP 1000
#define NBUCK 65536
#define CAP 16384
#define IMAX 2048
#define ECAP 10240
#define MWF 188           // ceil(6000/32)
#define WINF 0.300030518f // 0.3 widened by ~2^-13 (safety margin on the pruning bound)

// ---------------- scratch ----------------
__device__ unsigned int       g_hist[BB * NBUCK];
__device__ unsigned int       g_scat[BB * NBUCK];
__device__ unsigned int       g_off[BB * NBUCK];
__device__ int                g_thresh[BB];
__device__ int                g_need_full[BB];
__device__ unsigned long long g_sorted[BB * CAP];
__device__ float4             g_boxes[BB * PRE];
__device__ float              g_area[BB * PRE];
__device__ int                g_sidx[BB * IMAX];    // y1-rank -> score-order index
__device__ float4             g_sbox[BB * IMAX];    // boxes in y1-rank order
__device__ int                g_ecnt[BB];
__device__ int                g_edges[BB * ECAP];   // (i<<16)|j, i<j in score order

// ---------------- K0: zero counters ----------------
__global__ void zero_kernel() {
    int i = blockIdx.x * blockDim.x + threadIdx.x;
    int H = BB * NBUCK;
    if (i < H) { g_hist[i] = 0u; return; }
    i -= H;
    if (i < H) { g_scat[i] = 0u; return; }
    i -= H;
    if (i < BB) { g_ecnt[i] = 0; return; }
    i -= BB;
    if (i < BB) g_need_full[i] = 0;
}

__device__ __forceinline__ int bucket_of(float s) {
    int bk = (int)(s * 65536.0f);
    return max(0, min(bk, NBUCK - 1));
}

// ---------------- K1: histogram (float4: 2 scores per load) ----------------
__global__ void hist_kernel(const float* __restrict__ probs) {
    int g = blockIdx.x * 256 + threadIdx.x;            // BB*NN/2 threads
    float4 v = ((const float4*)probs)[g];
    int b = g >> 17;
    atomicAdd(&g_hist[b * NBUCK + bucket_of(v.y)], 1u);
    atomicAdd(&g_hist[b * NBUCK + bucket_of(v.w)], 1u);
}

// ---------------- K2: suffix-scan -> offsets + threshold ----------------
__global__ void scan_kernel() {
    __shared__ int part[1024];
    int b = blockIdx.x, t = threadIdx.x;
    const unsigned int* h = &g_hist[b * NBUCK];
    unsigned int* off = &g_off[b * NBUCK];
    int top = NBUCK - t * 64 - 1;
    int s = 0;
    #pragma unroll 8
    for (int k = 0; k < 64; ++k) s += (int)h[top - k];
    part[t] = s;
    __syncthreads();
    int mysum = s;
    for (int o = 1; o < 1024; o <<= 1) {
        int v = (t >= o) ? part[t - o] : 0;
        __syncthreads();
        part[t] += v;
        __syncthreads();
    }
    int running = part[t] - mysum;
    for (int bk = top; bk > top - 64; --bk) {
        unsigned int c = h[bk];
        off[bk] = (unsigned int)running;
        if (running < PRE && running + (int)c >= PRE) g_thresh[b] = bk;
        running += (int)c;
    }
}

// ---------------- K3: scatter candidates into bucket segments ----------------
__global__ void scatter_kernel(const float* __restrict__ probs) {
    int g = blockIdx.x * 256 + threadIdx.x;
    float4 v = ((const float4*)probs)[g];
    int b = g >> 17;
    int th = g_thresh[b];
    unsigned int n0 = (unsigned int)((g & 131071) * 2);
    #pragma unroll
    for (int e = 0; e < 2; ++e) {
        float s = e ? v.w : v.y;
        unsigned int n = n0 + e;
        int bk = bucket_of(s);
        if (bk >= th) {
            unsigned int pos = g_off[b * NBUCK + bk] +
                               atomicAdd(&g_scat[b * NBUCK + bk], 1u);
            if (pos < CAP)
                g_sorted[b * CAP + pos] =
                    ((unsigned long long)__float_as_uint(s) << 32) | (~n);
        }
    }
}

// ---------------- K4: per-bucket insertion sort (descending) ----------------
__global__ void bsort_kernel() {
    int g = blockIdx.x * 256 + threadIdx.x;
    int b = g >> 16, bk = g & (NBUCK - 1);
    if (bk < g_thresh[b]) return;
    int cnt = (int)g_hist[b * NBUCK + bk];
    if (cnt <= 1) return;
    int s0 = (int)g_off[b * NBUCK + bk];
    if (s0 >= CAP) return;
    int e0 = min(s0 + cnt, CAP);
    unsigned long long* a = &g_sorted[b * CAP];
    for (int i = s0 + 1; i < e0; ++i) {
        unsigned long long key = a[i];
        int j = i - 1;
        while (j >= s0 && a[j] < key) { a[j + 1] = a[j]; --j; }
        a[j + 1] = key;
    }
}

// ---------------- K5: decode top-PRE boxes (exact reference arithmetic) ----------------
__global__ void decode_kernel(const float* __restrict__ bbox,
                              const float* __restrict__ anchors) {
    int j = blockIdx.x * 256 + threadIdx.x;
    int b = blockIdx.y;
    if (j >= PRE) return;
    unsigned long long key = g_sorted[b * CAP + j];
    unsigned int n = ~(unsigned int)(key & 0xFFFFFFFFull);
    size_t base = (size_t)b * NN + n;
    float4 a = ((const float4*)anchors)[base];
    float4 r = ((const float4*)bbox)[base];
    float d0 = __fmul_rn(r.x, 0.1f), d1 = __fmul_rn(r.y, 0.1f);
    float d2 = __fmul_rn(r.z, 0.2f), d3 = __fmul_rn(r.w, 0.2f);
    float hh = __fsub_rn(a.z, a.x), ww = __fsub_rn(a.w, a.y);
    float cy = __fadd_rn(a.x, __fmul_rn(0.5f, hh));
    float cx = __fadd_rn(a.y, __fmul_rn(0.5f, ww));
    cy = __fadd_rn(cy, __fmul_rn(d0, hh));
    cx = __fadd_rn(cx, __fmul_rn(d1, ww));
    hh = __fmul_rn(hh, expf(d2));
    ww = __fmul_rn(ww, expf(d3));
    float y1 = __fsub_rn(cy, __fmul_rn(0.5f, hh));
    float x1 = __fsub_rn(cx, __fmul_rn(0.5f, ww));
    float y2 = __fadd_rn(cy, __fmul_rn(0.5f, hh));
    float x2 = __fadd_rn(cx, __fmul_rn(0.5f, ww));
    y1 = fminf(fmaxf(y1, 0.f), 1.f);
    x1 = fminf(fmaxf(x1, 0.f), 1.f);
    y2 = fminf(fmaxf(y2, 0.f), 1.f);
    x2 = fminf(fmaxf(x2, 0.f), 1.f);
    g_boxes[b * PRE + j] = make_float4(y1, x1, y2, x2);
    g_area[b * PRE + j] = __fmul_rn(__fsub_rn(y2, y1), __fsub_rn(x2, x1));
}

// ---------------- K6: sort top-IMAX boxes by y1 (per-batch bitonic) ----------------
__global__ void sorty_kernel() {
    __shared__ unsigned long long sk[IMAX];
    int b = blockIdx.x, t = threadIdx.x;
    for (int i = t; i < IMAX; i += 1024) {
        float y1 = g_boxes[b * PRE + i].x;               // y1 >= 0 -> bits order-preserving
        sk[i] = ((unsigned long long)__float_as_uint(y1) << 32) | (unsigned int)i;
    }
    __syncthreads();
    for (int k = 2; k <= IMAX; k <<= 1) {
        for (int j = k >> 1; j > 0; j >>= 1) {
            for (int i = t; i < IMAX; i += 1024) {
                int ixj = i ^ j;
                if (ixj > i) {
                    unsigned long long a = sk[i], c = sk[ixj];
                    bool sw = ((i & k) == 0) ? (a > c) : (a < c);   // ascending
                    if (sw) { sk[i] = c; sk[ixj] = a; }
                }
            }
            __syncthreads();
        }
    }
    for (int i = t; i < IMAX; i += 1024) {
        int idx = (int)(unsigned int)(sk[i] & 0xFFFFFFFFull);
        g_sidx[b * IMAX + i] = idx;
        g_sbox[b * IMAX + i] = g_boxes[b * PRE + idx];
    }
}

// ---------------- K7: sweep — emit suppression edges (IoU>0.7, i<j<IMAX) ----------------
__global__ void sweep_kernel() {
    int b = blockIdx.y;
    int r = blockIdx.x * 8 + (threadIdx.x >> 5);         // y1-rank, 0..IMAX-1
    int lane = threadIdx.x & 31;
    float4 br = g_sbox[b * IMAX + r];
    int   ir = g_sidx[b * IMAX + r];
    float hr = br.z - br.x;
    float ar = __fmul_rn(__fsub_rn(br.z, br.x), __fsub_rn(br.w, br.y));
    float wy = WINF * hr;

    // forward sweep: r is the lower-y1 box; covers Dy <= WINF*h_lower
    for (int j0 = r + 1 + lane; ; j0 += 32) {
        bool ok = j0 < IMAX;
        float4 bj; float diff = 3.0e38f;
        if (ok) { bj = g_sbox[b * IMAX + j0]; diff = bj.x - br.x; }
        bool in = ok && (diff <= wy);
        unsigned int bal = __ballot_sync(0xFFFFFFFFu, in);
        if (in) {
            float yy1 = fmaxf(br.x, bj.x), xx1 = fmaxf(br.y, bj.y);
            float yy2 = fminf(br.z, bj.z), xx2 = fminf(br.w, bj.w);
            float ihh = __fsub_rn(yy2, yy1), iww = __fsub_rn(xx2, xx1);
            if (ihh > 0.f && iww > 0.f) {
                float inter = __fmul_rn(ihh, iww);
                float aj = __fmul_rn(__fsub_rn(bj.z, bj.x), __fsub_rn(bj.w, bj.y));
                float den = __fadd_rn(__fsub_rn(__fadd_rn(ar, aj), inter), 1e-8f);
                if (__fdiv_rn(inter, den) > 0.7f) {
                    int jj = g_sidx[b * IMAX + j0];
                    int lo = min(ir, jj), hi = max(ir, jj);
                    int pos = atomicAdd(&g_ecnt[b], 1);
                    if (pos < ECAP) g_edges[b * ECAP + pos] = (lo << 16) | hi;
                }
            }
        }
        if (bal != 0xFFFFFFFFu) break;                   // sorted: first out ends window
    }

    // backward sweep: r is the upper-y1 box; covers Dy <= WINF*h_upper,
    // skipping pairs already covered forward (Dy <= WINF*h_lower)
    for (int j0 = r - 1 - lane; ; j0 -= 32) {
        bool ok = j0 >= 0;
        float4 bj; float diff = 3.0e38f;
        if (ok) { bj = g_sbox[b * IMAX + j0]; diff = br.x - bj.x; }
        bool in = ok && (diff <= wy);
        unsigned int bal = __ballot_sync(0xFFFFFFFFu, in);
        if (in) {
            float hj = bj.z - bj.x;
            if (!(diff <= WINF * hj)) {                  // not covered by forward sweep
                float yy1 = fmaxf(br.x, bj.x), xx1 = fmaxf(br.y, bj.y);
                float yy2 = fminf(br.z, bj.z), xx2 = fminf(br.w, bj.w);
                float ihh = __fsub_rn(yy2, yy1), iww = __fsub_rn(xx2, xx1);
                if (ihh > 0.f && iww > 0.f) {
                    float inter = __fmul_rn(ihh, iww);
                    float aj = __fmul_rn(__fsub_rn(bj.z, bj.x), __fsub_rn(bj.w, bj.y));
                    float den = __fadd_rn(__fsub_rn(__fadd_rn(ar, aj), inter), 1e-8f);
                    if (__fdiv_rn(inter, den) > 0.7f) {
                        int jj = g_sidx[b * IMAX + j0];
                        int lo = min(ir, jj), hi = max(ir, jj);
                        int pos = atomicAdd(&g_ecnt[b], 1);
                        if (pos < ECAP) g_edges[b * ECAP + pos] = (lo << 16) | hi;
                    }
                }
            }
        }
        if (bal != 0xFFFFFFFFu) break;
    }
}

// ---------------- K8: greedy over shared-memory CSR ----------------
__global__ void greedy_kernel(float4* __restrict__ out) {
    __shared__ int cnt[IMAX];           // counts -> cursor
    __shared__ int off[IMAX + 1];
    __shared__ unsigned short adj[ECAP];
    __shared__ unsigned int mask[IMAX / 32];
    __shared__ unsigned short sel[PROP];
    __shared__ int part[256];
    __shared__ int s_nsel, s_flag;
    int b = blockIdx.x, t = threadIdx.x;
    int E = g_ecnt[b];
    if (E > ECAP) {                                     // overflow -> exact fallback
        if (t == 0) g_need_full[b] = 1;
        return;
    }
    for (int i = t; i < IMAX; i += 256) cnt[i] = 0;
    for (int i = t; i < IMAX / 32; i += 256) mask[i] = 0xFFFFFFFFu;
    __syncthreads();
    for (int e = t; e < E; e += 256)
        atomicAdd(&cnt[g_edges[b * ECAP + e] >> 16], 1);
    __syncthreads();
    // exclusive prefix: 8 per thread + block scan
    int base8 = t * 8, loc = 0;
    #pragma unroll
    for (int k = 0; k < 8; ++k) loc += cnt[base8 + k];
    part[t] = loc;
    __syncthreads();
    for (int o = 1; o < 256; o <<= 1) {
        int v = (t >= o) ? part[t - o] : 0;
        __syncthreads();
        part[t] += v;
        __syncthreads();
    }
    int run = part[t] - loc;
    #pragma unroll
    for (int k = 0; k < 8; ++k) { int c = cnt[base8 + k]; off[base8 + k] = run; run += c; }
    if (t == 255) off[IMAX] = run;
    __syncthreads();
    #pragma unroll
    for (int k = 0; k < 8; ++k) cnt[base8 + k] = off[base8 + k];   // cursor
    __syncthreads();
    for (int e = t; e < E; e += 256) {
        int ed = g_edges[b * ECAP + e];
        int pos = atomicAdd(&cnt[ed >> 16], 1);
        adj[pos] = (unsigned short)(ed & 0xFFFF);
    }
    __syncthreads();
    if (t == 0) {
        int nsel = 0;
        for (int wd = 0; wd < IMAX / 32 && nsel < PROP; ++wd) {
            unsigned int word = mask[wd];
            while (word) {
                int bit = __ffs(word) - 1;
                word &= word - 1;
                int i = wd * 32 + bit;
                sel[nsel++] = (unsigned short)i;
                if (nsel == PROP) break;
                int s0 = off[i], s1 = off[i + 1];
                for (int e = s0; e < s1; ++e) {
                    int j = adj[e];                     // j > i always
                    int jw = j >> 5;
                    unsigned int bm = ~(1u << (j & 31));
                    if (jw == wd) word &= bm;
                    else mask[jw] &= bm;
                }
            }
        }
        s_nsel = nsel;
        s_flag = (nsel < PROP) ? 1 : 0;
        if (nsel < PROP) g_need_full[b] = 1;
    }
    __syncthreads();
    if (s_flag) return;
    int nsel = s_nsel;
    for (int k = t; k < PROP; k += 256)
        out[b * PROP + k] = (k < nsel) ? g_boxes[b * PRE + sel[k]]
                                       : make_float4(0.f, 0.f, 0.f, 0.f);
}

// ---------------- K9: exact full greedy fallback (normally a no-op) ----------------
__global__ void greedy_full_kernel(float4* __restrict__ out) {
    int b = blockIdx.x, t = threadIdx.x;
    if (!g_need_full[b]) return;
    __shared__ unsigned int mask[MWF];
    __shared__ int sel[PROP];
    __shared__ int s_pivot, s_nsel;
    for (int i = t; i < MWF; i += blockDim.x)
        mask[i] = (i < 187) ? 0xFFFFFFFFu : 0x0000FFFFu;
    if (t == 0) s_nsel = 0;
    __syncthreads();
    while (true) {
        if (t == 0) {
            int p = -1;
            if (s_nsel < PROP) {
                for (int wd = 0; wd < MWF; ++wd) {
                    unsigned int w = mask[wd];
                    if (w) { p = wd * 32 + __ffs(w) - 1; break; }
                }
            }
            s_pivot = p;
            if (p >= 0) { sel[s_nsel] = p; s_nsel++; }
        }
        __syncthreads();
        int p = s_pivot;
        if (p < 0) break;
        float4 bp = g_boxes[b * PRE + p];
        float  ap = g_area[b * PRE + p];
        if (t == 0) atomicAnd(&mask[p >> 5], ~(1u << (p & 31)));
        for (int j = p + 1 + t; j < PRE; j += blockDim.x) {
            if (!((mask[j >> 5] >> (j & 31)) & 1u)) continue;
            float4 bj = g_boxes[b * PRE + j];
            float yy1 = fmaxf(bp.x, bj.x), xx1 = fmaxf(bp.y, bj.y);
            float yy2 = fminf(bp.z, bj.z), xx2 = fminf(bp.w, bj.w);
            float ihh = __fsub_rn(yy2, yy1), iww = __fsub_rn(xx2, xx1);
            if (ihh <= 0.f || iww <= 0.f) continue;
            float inter = __fmul_rn(ihh, iww);
            float den = __fadd_rn(__fsub_rn(__fadd_rn(ap, g_area[b * PRE + j]), inter), 1e-8f);
            if (__fdiv_rn(inter, den) > 0.7f)
                atomicAnd(&mask[j >> 5], ~(1u << (j & 31)));
        }
        __syncthreads();
    }
    int nsel = s_nsel;
    for (int k = t; k < PROP; k += blockDim.x)
        out[b * PROP + k] = (k < nsel) ? g_boxes[b * PRE + sel[k]]
                                       : make_float4(0.f, 0.f, 0.f, 0.f);
}

// ---------------- launch ----------------
extern "C" void kernel_launch(void* const* d_in, const int* in_sizes, int n_in,
                              void* d_out, int out_size) {
    const float* probs   = (const float*)d_in[0];
    const float* bbox    = (const float*)d_in[1];
    const float* anchors = (const float*)d_in[2];

    int zeroTot = 2 * BB * NBUCK + 2 * BB;
    zero_kernel<<<(zeroTot + 255) / 256, 256>>>();
    hist_kernel<<<(BB * NN / 2) / 256, 256>>>(probs);
    scan_kernel<<<BB, 1024>>>();
    scatter_kernel<<<(BB * NN / 2) / 256, 256>>>(probs);
    bsort_kernel<<<(BB * NBUCK) / 256, 256>>>();
    decode_kernel<<<dim3((PRE + 255) / 256, BB), 256>>>(bbox, anchors);
    sorty_kernel<<<BB, 1024>>>();
    sweep_kernel<<<dim3(IMAX / 8, BB), 256>>>();
    greedy_kernel<<<BB, 256>>>((float4*)d_out);
    greedy_full_kernel<<<BB, 256>>>((float4*)d_out);
}